// round 12
// baseline (speedup 1.0000x reference)
#include <cuda_runtime.h>
#include <cuda_bf16.h>

// Problem constants (fixed by the reference)
#define B_      8
#define N_      4096
#define C_      128
#define K_      16
#define NPOINT_ 1024   // N/4

typedef unsigned long long ull;

// Scratch: transposed feature map fmT[(b*N + n)*C + c] = feature_map[b, c, n]
__device__ float g_fmT[B_ * N_ * C_];          // 16 MB
__device__ int   g_cents[B_ * NPOINT_];        // FPS centroid indices

// ---------------------------------------------------------------------------
// Packed f32x2 helpers (sm_103a). Per-lane .rn rounding == scalar __fadd_rn /
// __fsub_rn / __fmul_rn, so results are bit-exact vs the scalar version.
// ---------------------------------------------------------------------------
__device__ __forceinline__ ull pack2(float lo, float hi) {
    ull r;
    asm("mov.b64 %0, {%1, %2};" : "=l"(r) : "f"(lo), "f"(hi));
    return r;
}
__device__ __forceinline__ void unpack2(ull v, float& lo, float& hi) {
    asm("mov.b64 {%0, %1}, %2;" : "=f"(lo), "=f"(hi) : "l"(v));
}
__device__ __forceinline__ ull add2(ull a, ull b) {
    ull r;
    asm("add.rn.f32x2 %0, %1, %2;" : "=l"(r) : "l"(a), "l"(b));
    return r;
}
__device__ __forceinline__ ull sub2(ull a, ull b) {
    ull r;
    asm("sub.rn.f32x2 %0, %1, %2;" : "=l"(r) : "l"(a), "l"(b));
    return r;
}
__device__ __forceinline__ ull mul2(ull a, ull b) {
    ull r;
    asm("mul.rn.f32x2 %0, %1, %2;" : "=l"(r) : "l"(a), "l"(b));
    return r;
}

// ---------------------------------------------------------------------------
// Fused kernel: blocks 0..7 run FPS (one per batch); blocks 8.. run transpose
// tiles. The transpose (memory-bound, ~4096 blocks) fills the ~140 SMs the
// FPS leaves idle, hiding it entirely.
// ---------------------------------------------------------------------------
__global__ __launch_bounds__(256)
void fps_transpose_kernel(const float* __restrict__ vert,
                          const float* __restrict__ fm,
                          float* __restrict__ vpool) {
    // ---- transpose part ----------------------------------------------------
    if (blockIdx.x >= B_) {
        __shared__ float tile[32][33];
        const int t  = blockIdx.x - B_;          // 0 .. 4095
        const int n0 = (t & 127) * 32;           // N/32 = 128
        const int c0 = ((t >> 7) & 3) * 32;      // C/32 = 4
        const int b  = t >> 9;
        const int tx = threadIdx.x & 31, ty = threadIdx.x >> 5;

        const float* src = fm + (long)b * C_ * N_;
#pragma unroll
        for (int j = 0; j < 4; ++j) {
            int c = c0 + ty + 8 * j;
            tile[ty + 8 * j][tx] = src[(long)c * N_ + (n0 + tx)];
        }
        __syncthreads();
        float* dst = g_fmT + (long)b * N_ * C_;
#pragma unroll
        for (int j = 0; j < 4; ++j) {
            int n = n0 + ty + 8 * j;
            dst[(long)n * C_ + (c0 + tx)] = tile[tx][ty + 8 * j];
        }
        return;
    }

    // ---- FPS part: 256 threads (8 warps), 16 consecutive points/thread ----
    __shared__ __align__(16) unsigned s_val[2][8];
    __shared__ float4   s_rec[2][8];   // (x, y, z, unused) of per-warp winner

    const int b    = blockIdx.x;
    const int tid  = threadIdx.x;
    const int lane = tid & 31;
    const int warp = tid >> 5;

    const float* vb = vert + (long)b * 3 * N_;

    // coalesced float4 loads: thread owns points 16*tid .. 16*tid+15
    ull xp[8], yp[8], zp[8];
#pragma unroll
    for (int q = 0; q < 4; ++q) {
        const float4 xv = *(const float4*)(vb + 16 * tid + 4 * q);
        const float4 yv = *(const float4*)(vb + N_ + 16 * tid + 4 * q);
        const float4 zv = *(const float4*)(vb + 2 * N_ + 16 * tid + 4 * q);
        xp[2 * q] = pack2(xv.x, xv.y); xp[2 * q + 1] = pack2(xv.z, xv.w);
        yp[2 * q] = pack2(yv.x, yv.y); yp[2 * q + 1] = pack2(yv.z, yv.w);
        zp[2 * q] = pack2(zv.x, zv.y); zp[2 * q + 1] = pack2(zv.z, zv.w);
    }

    float d[16];
#pragma unroll
    for (int j = 0; j < 16; ++j) d[j] = 1e10f;

    // Seed: centroid 0 is point 0 — all threads read it straight from gmem
    // (L1/L2 broadcast, one time). Matches the reference scan start.
    float cx = __ldg(vb);
    float cy = __ldg(vb + N_);
    float cz = __ldg(vb + 2 * N_);
    if (tid == 0) {
        g_cents[b * NPOINT_] = 0;
        vpool[((long)b * 3 + 0) * NPOINT_] = cx;
        vpool[((long)b * 3 + 1) * NPOINT_] = cy;
        vpool[((long)b * 3 + 2) * NPOINT_] = cz;
    }

    // winner-lane state persists across the barrier in registers
    float px = 0.f, py = 0.f, pz = 0.f;
    int   myn = 0;

    for (int it = 1; it < NPOINT_; ++it) {
        const int P = it & 1;

        const ull c2x = pack2(cx, cx);
        const ull c2y = pack2(cy, cy);
        const ull c2z = pack2(cz, cz);

        // dist = (dx*dx + dy*dy) + dz*dz, two points per packed op, exact rn
#pragma unroll
        for (int k = 0; k < 8; ++k) {
            ull t, s;
            float q0, q1;
            t = sub2(xp[k], c2x); s = mul2(t, t);
            t = sub2(yp[k], c2y); s = add2(s, mul2(t, t));
            t = sub2(zp[k], c2z); s = add2(s, mul2(t, t));
            unpack2(s, q0, q1);
            d[2 * k]     = fminf(d[2 * k], q0);
            d[2 * k + 1] = fminf(d[2 * k + 1], q1);
        }

        // max tree with group maxima g0 = max(d0..7), g1 = max(d8..15)
        const float g0 = fmaxf(fmaxf(fmaxf(d[0], d[1]), fmaxf(d[2], d[3])),
                               fmaxf(fmaxf(d[4], d[5]), fmaxf(d[6], d[7])));
        const float g1 = fmaxf(fmaxf(fmaxf(d[8], d[9]), fmaxf(d[10], d[11])),
                               fmaxf(fmaxf(d[12], d[13]), fmaxf(d[14], d[15])));
        const float bestv = fmaxf(g0, g1);

        // warp argmax, first-occurrence ties: REDUX max + min lane via ballot
        const unsigned bv    = __float_as_uint(bestv);   // bestv >= 0 -> monotonic
        const unsigned wmax  = __reduce_max_sync(0xffffffffu, bv);
        const unsigned mask  = __ballot_sync(0xffffffffu, bv == wmax);
        const int      wlane = __ffs(mask) - 1;

        if (lane == wlane) {
            // first-occurrence local index: group select, equality mask, ffs
            const int gsel = (g0 == bestv) ? 0 : 1;
            const float u0 = gsel ? d[8]  : d[0];
            const float u1 = gsel ? d[9]  : d[1];
            const float u2 = gsel ? d[10] : d[2];
            const float u3 = gsel ? d[11] : d[3];
            const float u4 = gsel ? d[12] : d[4];
            const float u5 = gsel ? d[13] : d[5];
            const float u6 = gsel ? d[14] : d[6];
            const float u7 = gsel ? d[15] : d[7];
            const unsigned em =
                (unsigned)(u0 == bestv)       | ((unsigned)(u1 == bestv) << 1) |
                ((unsigned)(u2 == bestv) << 2) | ((unsigned)(u3 == bestv) << 3) |
                ((unsigned)(u4 == bestv) << 4) | ((unsigned)(u5 == bestv) << 5) |
                ((unsigned)(u6 == bestv) << 6) | ((unsigned)(u7 == bestv) << 7);
            const int p = (gsel << 3) | (__ffs(em) - 1);
            myn = (tid << 4) | p;
            // coords from gmem (L1-hit broadcast of the warm vertex rows)
            px = __ldg(vb + myn);
            py = __ldg(vb + N_ + myn);
            pz = __ldg(vb + 2 * N_ + myn);
            s_val[P][warp] = wmax;
            s_rec[P][warp] = make_float4(px, py, pz, 0.f);
        }
        __syncthreads();   // the ONLY barrier per iteration (ping-pong buffers)

        // level 2: static first-occurrence max over the 8 warp slots
        const uint4 A  = *(const uint4*)&s_val[P][0];
        const uint4 Bv = *(const uint4*)&s_val[P][4];
        unsigned m01 = (A.x >= A.y) ? A.x : A.y;   int w01 = (A.x >= A.y) ? 0 : 1;
        unsigned m23 = (A.z >= A.w) ? A.z : A.w;   int w23 = (A.z >= A.w) ? 2 : 3;
        unsigned m45 = (Bv.x >= Bv.y) ? Bv.x : Bv.y; int w45 = (Bv.x >= Bv.y) ? 4 : 5;
        unsigned m67 = (Bv.z >= Bv.w) ? Bv.z : Bv.w; int w67 = (Bv.z >= Bv.w) ? 6 : 7;
        unsigned m03 = (m01 >= m23) ? m01 : m23;   int w03 = (m01 >= m23) ? w01 : w23;
        unsigned m47 = (m45 >= m67) ? m45 : m67;   int w47 = (m45 >= m67) ? w45 : w67;
        const int wwin = (m03 >= m47) ? w03 : w47;

        const float4 r = s_rec[P][wwin];   // LDS.128 broadcast
        cx = r.x; cy = r.y; cz = r.z;

        if (warp == wwin && lane == wlane) {   // unique global winner
            g_cents[b * NPOINT_ + it] = myn;
            vpool[((long)b * 3 + 0) * NPOINT_ + it] = px;
            vpool[((long)b * 3 + 1) * NPOINT_ + it] = py;
            vpool[((long)b * 3 + 2) * NPOINT_ + it] = pz;
        }
    }
}

// ---------------------------------------------------------------------------
// Kernel C: gather K neighbors of each sampled point from fmT, max-pool over K,
// write feature_map_pool (B,C,NPOINT). One block per sampled point, c = tid.
// idx dtype (int32 vs int64) detected from data: int64 high words are all 0.
// ---------------------------------------------------------------------------
__global__ void gather_max_kernel(const void* __restrict__ idxp,
                                  float* __restrict__ fpool) {
    const int bp = blockIdx.x;            // 0 .. B*NPOINT-1
    const int b  = bp >> 10;              // / NPOINT_
    const int i  = bp & (NPOINT_ - 1);
    const int c  = threadIdx.x;

    const int s = g_cents[bp];

    const int* i32 = (const int*)idxp;
    const bool is64 = ((i32[1] | i32[3] | i32[5]) == 0);

    const long base = ((long)(b * N_ + s)) * K_;
    const long long* i64 = (const long long*)idxp;

    float m = -3.4028235e38f;
#pragma unroll
    for (int k = 0; k < K_; ++k) {
        long g = is64 ? (long)i64[base + k] : (long)i32[base + k];
        m = fmaxf(m, g_fmT[g * C_ + c]);
    }
    fpool[((long)b * C_ + c) * NPOINT_ + i] = m;
}

// ---------------------------------------------------------------------------
extern "C" void kernel_launch(void* const* d_in, const int* in_sizes, int n_in,
                              void* d_out, int out_size) {
    const float* vert = (const float*)d_in[0];   // (B,3,N)   float32
    const float* fm   = (const float*)d_in[1];   // (B,C,N)   float32
    const void*  idx  = d_in[2];                 // (B*N*K,)  int64 or int32

    float* out   = (float*)d_out;
    float* vpool = out;                          // (B,3,NPOINT)
    float* fpool = out + (long)B_ * 3 * NPOINT_; // (B,C,NPOINT)

    // 8 FPS blocks + 4096 transpose tiles in one launch (transpose hides
    // under FPS on the otherwise-idle SMs)
    fps_transpose_kernel<<<B_ + (N_ / 32) * (C_ / 32) * B_, 256>>>(vert, fm, vpool);
    gather_max_kernel<<<B_ * NPOINT_, C_>>>(idx, fpool);
}

// round 14
// speedup vs baseline: 1.1490x; 1.1490x over previous
#include <cuda_runtime.h>
#include <cuda_bf16.h>

// Problem constants (fixed by the reference)
#define B_      8
#define N_      4096
#define C_      128
#define K_      16
#define NPOINT_ 1024   // N/4

typedef unsigned long long ull;

// Scratch: transposed feature map fmT[(b*N + n)*C + c] = feature_map[b, c, n]
__device__ float g_fmT[B_ * N_ * C_];          // 16 MB
__device__ int   g_cents[B_ * NPOINT_];        // FPS centroid indices

// ---------------------------------------------------------------------------
// Packed f32x2 helpers (sm_103a). Per-lane .rn rounding == scalar __fadd_rn /
// __fsub_rn / __fmul_rn, so results are bit-exact vs the scalar version.
// ---------------------------------------------------------------------------
__device__ __forceinline__ ull pack2(float lo, float hi) {
    ull r;
    asm("mov.b64 %0, {%1, %2};" : "=l"(r) : "f"(lo), "f"(hi));
    return r;
}
__device__ __forceinline__ void unpack2(ull v, float& lo, float& hi) {
    asm("mov.b64 {%0, %1}, %2;" : "=f"(lo), "=f"(hi) : "l"(v));
}
__device__ __forceinline__ ull add2(ull a, ull b) {
    ull r;
    asm("add.rn.f32x2 %0, %1, %2;" : "=l"(r) : "l"(a), "l"(b));
    return r;
}
__device__ __forceinline__ ull sub2(ull a, ull b) {
    ull r;
    asm("sub.rn.f32x2 %0, %1, %2;" : "=l"(r) : "l"(a), "l"(b));
    return r;
}
__device__ __forceinline__ ull mul2(ull a, ull b) {
    ull r;
    asm("mul.rn.f32x2 %0, %1, %2;" : "=l"(r) : "l"(a), "l"(b));
    return r;
}

// ---------------------------------------------------------------------------
// Kernel A: transpose feature_map (B,C,N) -> fmT (B*N, C)  (separate launch;
// fusing it into FPS regressed in R12 via co-residency issue stealing)
// ---------------------------------------------------------------------------
__global__ void transpose_kernel(const float* __restrict__ fm) {
    __shared__ float tile[32][33];
    const int b  = blockIdx.z;
    const int n0 = blockIdx.x * 32;
    const int c0 = blockIdx.y * 32;
    const int tx = threadIdx.x, ty = threadIdx.y;

    const float* src = fm + (long)b * C_ * N_;
#pragma unroll
    for (int j = 0; j < 4; ++j) {
        int c = c0 + ty + 8 * j;
        tile[ty + 8 * j][tx] = src[(long)c * N_ + (n0 + tx)];
    }
    __syncthreads();
    float* dst = g_fmT + (long)b * N_ * C_;
#pragma unroll
    for (int j = 0; j < 4; ++j) {
        int n = n0 + ty + 8 * j;
        dst[(long)n * C_ + (c0 + tx)] = tile[tx][ty + 8 * j];
    }
}

// ---------------------------------------------------------------------------
// Kernel B: farthest point sampling. One block per batch, 128 threads
// (4 warps = 1 per SMSP), 32 consecutive points per thread (n = tid*32 + j).
// fma floor is unchanged (work conserved); the serial tail shrinks:
//  - pre-barrier: REDUX + ballot + hierarchical first-occurrence index only
//  - winner stores (val, idx) — NO coordinate select on the critical lane
//  - post-barrier: 2x LDS.128 + 3-compare static tree over 4 warp slots,
//    then 3 uniform L1-hit LDGs fetch the centroid coords (all threads).
// First-occurrence argmax: indices ordered by (warp, lane, j); ties resolved
// by min lane (ballot+ffs), min group (>= chains), min element (ffs of mask).
// ---------------------------------------------------------------------------
__global__ __launch_bounds__(128, 1)
void fps_kernel(const float* __restrict__ vert, float* __restrict__ vpool) {
    __shared__ __align__(16) unsigned s_val[2][4];
    __shared__ __align__(16) int      s_n[2][4];

    const int b    = blockIdx.x;
    const int tid  = threadIdx.x;
    const int lane = tid & 31;
    const int warp = tid >> 5;

    const float* vb = vert + (long)b * 3 * N_;

    // coalesced float4 loads: thread owns points 32*tid .. 32*tid+31
    ull xp[16], yp[16], zp[16];
#pragma unroll
    for (int q = 0; q < 8; ++q) {
        const float4 xv = *(const float4*)(vb + 32 * tid + 4 * q);
        const float4 yv = *(const float4*)(vb + N_ + 32 * tid + 4 * q);
        const float4 zv = *(const float4*)(vb + 2 * N_ + 32 * tid + 4 * q);
        xp[2 * q] = pack2(xv.x, xv.y); xp[2 * q + 1] = pack2(xv.z, xv.w);
        yp[2 * q] = pack2(yv.x, yv.y); yp[2 * q + 1] = pack2(yv.z, yv.w);
        zp[2 * q] = pack2(zv.x, zv.y); zp[2 * q + 1] = pack2(zv.z, zv.w);
    }

    float d[32];
#pragma unroll
    for (int j = 0; j < 32; ++j) d[j] = 1e10f;

    // Seed: centroid 0 is point 0 — all threads read it straight from gmem
    // (L1/L2 broadcast, one time). Matches the reference scan start.
    float cx = __ldg(vb);
    float cy = __ldg(vb + N_);
    float cz = __ldg(vb + 2 * N_);
    if (tid == 0) {
        g_cents[b * NPOINT_] = 0;
        vpool[((long)b * 3 + 0) * NPOINT_] = cx;
        vpool[((long)b * 3 + 1) * NPOINT_] = cy;
        vpool[((long)b * 3 + 2) * NPOINT_] = cz;
    }

    for (int it = 1; it < NPOINT_; ++it) {
        const int P = it & 1;

        const ull c2x = pack2(cx, cx);
        const ull c2y = pack2(cy, cy);
        const ull c2z = pack2(cz, cz);

        // dist = (dx*dx + dy*dy) + dz*dz, two points per packed op, exact rn
#pragma unroll
        for (int k = 0; k < 16; ++k) {
            ull t, s;
            float q0, q1;
            t = sub2(xp[k], c2x); s = mul2(t, t);
            t = sub2(yp[k], c2y); s = add2(s, mul2(t, t));
            t = sub2(zp[k], c2z); s = add2(s, mul2(t, t));
            unpack2(s, q0, q1);
            d[2 * k]     = fminf(d[2 * k], q0);
            d[2 * k + 1] = fminf(d[2 * k + 1], q1);
        }

        // group maxima over 4 groups of 8 (first-occurrence order preserved)
        float g[4];
#pragma unroll
        for (int gq = 0; gq < 4; ++gq) {
            const float* dg = d + 8 * gq;
            g[gq] = fmaxf(fmaxf(fmaxf(dg[0], dg[1]), fmaxf(dg[2], dg[3])),
                          fmaxf(fmaxf(dg[4], dg[5]), fmaxf(dg[6], dg[7])));
        }
        const float bestv = fmaxf(fmaxf(g[0], g[1]), fmaxf(g[2], g[3]));

        // warp argmax, first-occurrence ties: REDUX max + min lane via ballot
        const unsigned bv    = __float_as_uint(bestv);   // bestv >= 0 -> monotonic
        const unsigned wmax  = __reduce_max_sync(0xffffffffu, bv);
        const unsigned mask  = __ballot_sync(0xffffffffu, bv == wmax);
        const int      wlane = __ffs(mask) - 1;

        if (lane == wlane) {
            // first-occurrence local index: min group with g==bestv, then
            // min element via equality-mask ffs. No coordinate selects here.
            const int gsel = (g[0] == bestv) ? 0
                           : (g[1] == bestv) ? 1
                           : (g[2] == bestv) ? 2 : 3;
            const float* dg = d + 8 * gsel;
            const unsigned em =
                 (unsigned)(dg[0] == bestv)        | ((unsigned)(dg[1] == bestv) << 1)
               | ((unsigned)(dg[2] == bestv) << 2) | ((unsigned)(dg[3] == bestv) << 3)
               | ((unsigned)(dg[4] == bestv) << 4) | ((unsigned)(dg[5] == bestv) << 5)
               | ((unsigned)(dg[6] == bestv) << 6) | ((unsigned)(dg[7] == bestv) << 7);
            const int j = (gsel << 3) | (__ffs(em) - 1);
            s_val[P][warp] = wmax;
            s_n[P][warp]   = (tid << 5) | j;
        }
        __syncthreads();   // the ONLY barrier per iteration (ping-pong buffers)

        // level 2: static first-occurrence max over the 4 warp slots
        const uint4 V  = *(const uint4*)&s_val[P][0];   // LDS.128
        const int4  I  = *(const int4*)&s_n[P][0];      // LDS.128
        unsigned m01 = (V.x >= V.y) ? V.x : V.y;  int n01 = (V.x >= V.y) ? I.x : I.y;
        unsigned m23 = (V.z >= V.w) ? V.z : V.w;  int n23 = (V.z >= V.w) ? I.z : I.w;
        const int nwin = (m01 >= m23) ? n01 : n23;

        // centroid coords: uniform L1-hit broadcast loads (rows are warm)
        cx = __ldg(vb + nwin);
        cy = __ldg(vb + N_ + nwin);
        cz = __ldg(vb + 2 * N_ + nwin);

        if (tid == 0) {
            g_cents[b * NPOINT_ + it] = nwin;
            vpool[((long)b * 3 + 0) * NPOINT_ + it] = cx;
            vpool[((long)b * 3 + 1) * NPOINT_ + it] = cy;
            vpool[((long)b * 3 + 2) * NPOINT_ + it] = cz;
        }
    }
}

// ---------------------------------------------------------------------------
// Kernel C: gather K neighbors of each sampled point from fmT, max-pool over K,
// write feature_map_pool (B,C,NPOINT). One block per sampled point, c = tid.
// idx dtype (int32 vs int64) detected from data: int64 high words are all 0.
// ---------------------------------------------------------------------------
__global__ void gather_max_kernel(const void* __restrict__ idxp,
                                  float* __restrict__ fpool) {
    const int bp = blockIdx.x;            // 0 .. B*NPOINT-1
    const int b  = bp >> 10;              // / NPOINT_
    const int i  = bp & (NPOINT_ - 1);
    const int c  = threadIdx.x;

    const int s = g_cents[bp];

    const int* i32 = (const int*)idxp;
    const bool is64 = ((i32[1] | i32[3] | i32[5]) == 0);

    const long base = ((long)(b * N_ + s)) * K_;
    const long long* i64 = (const long long*)idxp;

    float m = -3.4028235e38f;
#pragma unroll
    for (int k = 0; k < K_; ++k) {
        long g = is64 ? (long)i64[base + k] : (long)i32[base + k];
        m = fmaxf(m, g_fmT[g * C_ + c]);
    }
    fpool[((long)b * C_ + c) * NPOINT_ + i] = m;
}

// ---------------------------------------------------------------------------
extern "C" void kernel_launch(void* const* d_in, const int* in_sizes, int n_in,
                              void* d_out, int out_size) {
    const float* vert = (const float*)d_in[0];   // (B,3,N)   float32
    const float* fm   = (const float*)d_in[1];   // (B,C,N)   float32
    const void*  idx  = d_in[2];                 // (B*N*K,)  int64 or int32

    float* out   = (float*)d_out;
    float* vpool = out;                          // (B,3,NPOINT)
    float* fpool = out + (long)B_ * 3 * NPOINT_; // (B,C,NPOINT)

    transpose_kernel<<<dim3(N_ / 32, C_ / 32, B_), dim3(32, 8)>>>(fm);
    fps_kernel<<<B_, 128>>>(vert, vpool);
    gather_max_kernel<<<B_ * NPOINT_, C_>>>(idx, fpool);
}

// round 15
// speedup vs baseline: 1.1775x; 1.0248x over previous
#include <cuda_runtime.h>
#include <cuda_bf16.h>

// Problem constants (fixed by the reference)
#define B_      8
#define N_      4096
#define C_      128
#define K_      16
#define NPOINT_ 1024   // N/4

typedef unsigned long long ull;

// Scratch: transposed feature map fmT[(b*N + n)*C + c] = feature_map[b, c, n]
__device__ float g_fmT[B_ * N_ * C_];          // 16 MB
__device__ int   g_cents[B_ * NPOINT_];        // FPS centroid indices

// ---------------------------------------------------------------------------
// Packed f32x2 helpers (sm_103a). Per-lane .rn rounding == scalar __fadd_rn /
// __fsub_rn / __fmul_rn, so results are bit-exact vs the scalar version.
// ---------------------------------------------------------------------------
__device__ __forceinline__ ull pack2(float lo, float hi) {
    ull r;
    asm("mov.b64 %0, {%1, %2};" : "=l"(r) : "f"(lo), "f"(hi));
    return r;
}
__device__ __forceinline__ void unpack2(ull v, float& lo, float& hi) {
    asm("mov.b64 {%0, %1}, %2;" : "=f"(lo), "=f"(hi) : "l"(v));
}
__device__ __forceinline__ ull add2(ull a, ull b) {
    ull r;
    asm("add.rn.f32x2 %0, %1, %2;" : "=l"(r) : "l"(a), "l"(b));
    return r;
}
__device__ __forceinline__ ull sub2(ull a, ull b) {
    ull r;
    asm("sub.rn.f32x2 %0, %1, %2;" : "=l"(r) : "l"(a), "l"(b));
    return r;
}
__device__ __forceinline__ ull mul2(ull a, ull b) {
    ull r;
    asm("mul.rn.f32x2 %0, %1, %2;" : "=l"(r) : "l"(a), "l"(b));
    return r;
}

// ---------------------------------------------------------------------------
// Kernel A: transpose feature_map (B,C,N) -> fmT (B*N, C)  (separate launch;
// fusing it into FPS regressed in R12 via co-residency issue stealing)
// ---------------------------------------------------------------------------
__global__ void transpose_kernel(const float* __restrict__ fm) {
    __shared__ float tile[32][33];
    const int b  = blockIdx.z;
    const int n0 = blockIdx.x * 32;
    const int c0 = blockIdx.y * 32;
    const int tx = threadIdx.x, ty = threadIdx.y;

    const float* src = fm + (long)b * C_ * N_;
#pragma unroll
    for (int j = 0; j < 4; ++j) {
        int c = c0 + ty + 8 * j;
        tile[ty + 8 * j][tx] = src[(long)c * N_ + (n0 + tx)];
    }
    __syncthreads();
    float* dst = g_fmT + (long)b * N_ * C_;
#pragma unroll
    for (int j = 0; j < 4; ++j) {
        int n = n0 + ty + 8 * j;
        dst[(long)n * C_ + (c0 + tx)] = tile[tx][ty + 8 * j];
    }
}

// ---------------------------------------------------------------------------
// Kernel B: farthest point sampling. One block per batch, 128 threads
// (4 warps = 1 per SMSP), 32 consecutive points per thread (n = tid*32 + j).
// Tail restructured for minimum serial latency:
//  - local first-occurrence index computed BRANCHLESSLY by ALL lanes,
//    overlapping the REDUX latency (no divergent region pre-barrier)
//  - two REDUXes (max val, then max ~idx among ties) replace ballot+ffs
//  - one packed 64-bit key (val<<32 | ~idx) per warp: single @p STS.64,
//    level-2 = 2x LDS.128 + 3 ull max-compares (ties -> min idx automatically)
// First-occurrence argmax preserved exactly: indices ordered by (warp,lane,j).
// ---------------------------------------------------------------------------
__global__ __launch_bounds__(128, 1)
void fps_kernel(const float* __restrict__ vert, float* __restrict__ vpool) {
    __shared__ __align__(16) ull s_key[2][4];

    const int b    = blockIdx.x;
    const int tid  = threadIdx.x;
    const int lane = tid & 31;

    const float* vb = vert + (long)b * 3 * N_;

    // coalesced float4 loads: thread owns points 32*tid .. 32*tid+31
    ull xp[16], yp[16], zp[16];
#pragma unroll
    for (int q = 0; q < 8; ++q) {
        const float4 xv = *(const float4*)(vb + 32 * tid + 4 * q);
        const float4 yv = *(const float4*)(vb + N_ + 32 * tid + 4 * q);
        const float4 zv = *(const float4*)(vb + 2 * N_ + 32 * tid + 4 * q);
        xp[2 * q] = pack2(xv.x, xv.y); xp[2 * q + 1] = pack2(xv.z, xv.w);
        yp[2 * q] = pack2(yv.x, yv.y); yp[2 * q + 1] = pack2(yv.z, yv.w);
        zp[2 * q] = pack2(zv.x, zv.y); zp[2 * q + 1] = pack2(zv.z, zv.w);
    }

    float d[32];
#pragma unroll
    for (int j = 0; j < 32; ++j) d[j] = 1e10f;

    // Seed: centroid 0 is point 0 — all threads read it straight from gmem
    // (L1/L2 broadcast, one time). Matches the reference scan start.
    float cx = __ldg(vb);
    float cy = __ldg(vb + N_);
    float cz = __ldg(vb + 2 * N_);
    if (tid == 0) {
        g_cents[b * NPOINT_] = 0;
        vpool[((long)b * 3 + 0) * NPOINT_] = cx;
        vpool[((long)b * 3 + 1) * NPOINT_] = cy;
        vpool[((long)b * 3 + 2) * NPOINT_] = cz;
    }

    for (int it = 1; it < NPOINT_; ++it) {
        const int P = it & 1;

        const ull c2x = pack2(cx, cx);
        const ull c2y = pack2(cy, cy);
        const ull c2z = pack2(cz, cz);

        // dist = (dx*dx + dy*dy) + dz*dz, two points per packed op, exact rn
#pragma unroll
        for (int k = 0; k < 16; ++k) {
            ull t, s;
            float q0, q1;
            t = sub2(xp[k], c2x); s = mul2(t, t);
            t = sub2(yp[k], c2y); s = add2(s, mul2(t, t));
            t = sub2(zp[k], c2z); s = add2(s, mul2(t, t));
            unpack2(s, q0, q1);
            d[2 * k]     = fminf(d[2 * k], q0);
            d[2 * k + 1] = fminf(d[2 * k + 1], q1);
        }

        // group maxima over 4 groups of 8 (first-occurrence order preserved)
        float g[4];
#pragma unroll
        for (int gq = 0; gq < 4; ++gq) {
            const float* dg = d + 8 * gq;
            g[gq] = fmaxf(fmaxf(fmaxf(dg[0], dg[1]), fmaxf(dg[2], dg[3])),
                          fmaxf(fmaxf(dg[4], dg[5]), fmaxf(dg[6], dg[7])));
        }
        const float bestv = fmaxf(fmaxf(g[0], g[1]), fmaxf(g[2], g[3]));
        const unsigned bv = __float_as_uint(bestv);      // bestv >= 0 -> monotonic

        // REDUX #1 (max value over warp). Overlapped with it: every lane
        // computes its own first-occurrence local index branchlessly.
        const unsigned wmax = __reduce_max_sync(0xffffffffu, bv);

        const int gsel = (g[0] == bestv) ? 0
                       : (g[1] == bestv) ? 1
                       : (g[2] == bestv) ? 2 : 3;
        const float* dg = d + 8 * gsel;
        const unsigned em =
             (unsigned)(dg[0] == bestv)        | ((unsigned)(dg[1] == bestv) << 1)
           | ((unsigned)(dg[2] == bestv) << 2) | ((unsigned)(dg[3] == bestv) << 3)
           | ((unsigned)(dg[4] == bestv) << 4) | ((unsigned)(dg[5] == bestv) << 5)
           | ((unsigned)(dg[6] == bestv) << 6) | ((unsigned)(dg[7] == bestv) << 7);
        const int      myn  = (tid << 5) | (gsel << 3) | (__ffs(em) - 1);

        // REDUX #2: max(~idx) among value-ties == min idx (first occurrence)
        const unsigned cand = (bv == wmax) ? ~(unsigned)myn : 0u;
        const unsigned winv = __reduce_max_sync(0xffffffffu, cand);

        if (lane == 0)
            s_key[P][tid >> 5] = ((ull)wmax << 32) | winv;   // @p STS.64
        __syncthreads();   // the ONLY barrier per iteration (ping-pong buffers)

        // level 2: 3 packed max-compares; tie -> larger ~idx -> smaller idx
        const ulonglong2 kA = *(const ulonglong2*)&s_key[P][0];  // LDS.128
        const ulonglong2 kB = *(const ulonglong2*)&s_key[P][2];  // LDS.128
        const ull k01 = (kA.x >= kA.y) ? kA.x : kA.y;
        const ull k23 = (kB.x >= kB.y) ? kB.x : kB.y;
        const ull kw  = (k01 >= k23) ? k01 : k23;
        const int nwin = (int)(~(unsigned)kw);

        // centroid coords: uniform L1-hit broadcast loads (rows are warm)
        cx = __ldg(vb + nwin);
        cy = __ldg(vb + N_ + nwin);
        cz = __ldg(vb + 2 * N_ + nwin);

        if (tid == 0) {
            g_cents[b * NPOINT_ + it] = nwin;
            vpool[((long)b * 3 + 0) * NPOINT_ + it] = cx;
            vpool[((long)b * 3 + 1) * NPOINT_ + it] = cy;
            vpool[((long)b * 3 + 2) * NPOINT_ + it] = cz;
        }
    }
}

// ---------------------------------------------------------------------------
// Kernel C: gather K neighbors of each sampled point from fmT, max-pool over K,
// write feature_map_pool (B,C,NPOINT). One block per sampled point, c = tid.
// idx dtype (int32 vs int64) detected from data: int64 high words are all 0.
// ---------------------------------------------------------------------------
__global__ void gather_max_kernel(const void* __restrict__ idxp,
                                  float* __restrict__ fpool) {
    const int bp = blockIdx.x;            // 0 .. B*NPOINT-1
    const int b  = bp >> 10;              // / NPOINT_
    const int i  = bp & (NPOINT_ - 1);
    const int c  = threadIdx.x;

    const int s = g_cents[bp];

    const int* i32 = (const int*)idxp;
    const bool is64 = ((i32[1] | i32[3] | i32[5]) == 0);

    const long base = ((long)(b * N_ + s)) * K_;
    const long long* i64 = (const long long*)idxp;

    float m = -3.4028235e38f;
#pragma unroll
    for (int k = 0; k < K_; ++k) {
        long g = is64 ? (long)i64[base + k] : (long)i32[base + k];
        m = fmaxf(m, g_fmT[g * C_ + c]);
    }
    fpool[((long)b * C_ + c) * NPOINT_ + i] = m;
}

// ---------------------------------------------------------------------------
extern "C" void kernel_launch(void* const* d_in, const int* in_sizes, int n_in,
                              void* d_out, int out_size) {
    const float* vert = (const float*)d_in[0];   // (B,3,N)   float32
    const float* fm   = (const float*)d_in[1];   // (B,C,N)   float32
    const void*  idx  = d_in[2];                 // (B*N*K,)  int64 or int32

    float* out   = (float*)d_out;
    float* vpool = out;                          // (B,3,NPOINT)
    float* fpool = out + (long)B_ * 3 * NPOINT_; // (B,C,NPOINT)

    transpose_kernel<<<dim3(N_ / 32, C_ / 32, B_), dim3(32, 8)>>>(fm);
    fps_kernel<<<B_, 128>>>(vert, vpool);
    gather_max_kernel<<<B_ * NPOINT_, C_>>>(idx, fpool);
}

// round 17
// speedup vs baseline: 1.3668x; 1.1608x over previous
#include <cuda_runtime.h>
#include <cuda_bf16.h>

// Problem constants (fixed by the reference)
#define B_      8
#define N_      4096
#define C_      128
#define K_      16
#define NPOINT_ 1024   // N/4

typedef unsigned long long ull;

// Scratch: transposed feature map fmT[(b*N + n)*C + c] = feature_map[b, c, n]
__device__ float g_fmT[B_ * N_ * C_];          // 16 MB
__device__ int   g_cents[B_ * NPOINT_];        // FPS centroid indices

// ---------------------------------------------------------------------------
// Packed f32x2 helpers (sm_103a). Only add/sub/mul(/fma) exist in f32x2 form;
// per-lane .rn rounding == scalar __fadd_rn/__fsub_rn/__fmul_rn (bit-exact).
// min/max are done scalar (FMNMX selects an operand exactly, no rounding).
// ---------------------------------------------------------------------------
__device__ __forceinline__ ull pack2(float lo, float hi) {
    ull r;
    asm("mov.b64 %0, {%1, %2};" : "=l"(r) : "f"(lo), "f"(hi));
    return r;
}
__device__ __forceinline__ void unpack2(ull v, float& lo, float& hi) {
    asm("mov.b64 {%0, %1}, %2;" : "=f"(lo), "=f"(hi) : "l"(v));
}
__device__ __forceinline__ ull add2(ull a, ull b) {
    ull r;
    asm("add.rn.f32x2 %0, %1, %2;" : "=l"(r) : "l"(a), "l"(b));
    return r;
}
__device__ __forceinline__ ull sub2(ull a, ull b) {
    ull r;
    asm("sub.rn.f32x2 %0, %1, %2;" : "=l"(r) : "l"(a), "l"(b));
    return r;
}
__device__ __forceinline__ ull mul2(ull a, ull b) {
    ull r;
    asm("mul.rn.f32x2 %0, %1, %2;" : "=l"(r) : "l"(a), "l"(b));
    return r;
}

// ---------------------------------------------------------------------------
// Kernel A: transpose feature_map (B,C,N) -> fmT (B*N, C)  (separate launch;
// fusing it into FPS regressed in R12 via co-residency issue stealing)
// ---------------------------------------------------------------------------
__global__ void transpose_kernel(const float* __restrict__ fm) {
    __shared__ float tile[32][33];
    const int b  = blockIdx.z;
    const int n0 = blockIdx.x * 32;
    const int c0 = blockIdx.y * 32;
    const int tx = threadIdx.x, ty = threadIdx.y;

    const float* src = fm + (long)b * C_ * N_;
#pragma unroll
    for (int j = 0; j < 4; ++j) {
        int c = c0 + ty + 8 * j;
        tile[ty + 8 * j][tx] = src[(long)c * N_ + (n0 + tx)];
    }
    __syncthreads();
    float* dst = g_fmT + (long)b * N_ * C_;
#pragma unroll
    for (int j = 0; j < 4; ++j) {
        int n = n0 + ty + 8 * j;
        dst[(long)n * C_ + (c0 + tx)] = tile[tx][ty + 8 * j];
    }
}

// ---------------------------------------------------------------------------
// Kernel B: farthest point sampling. One block per batch, 128 threads
// (4 warps = 1 per SMSP), 32 consecutive points per thread (n = tid*32 + j).
// d[32] is indexed ONLY by constants (loops fully unrolled) -> stays in
// registers; no dynamic indexing (which demotes arrays to local memory).
// First-occurrence argmax preserved exactly:
//  - per-lane index via a flat 32-bit integer-equality mask (distances are
//    all >= +0, never -0/NaN, so bit equality == float equality) + ffs,
//    computed by ALL lanes branchlessly, overlapping REDUX #1 latency
//  - warp level: REDUX max(value), then REDUX max(~idx) among ties
//  - block level: packed 64-bit keys (val<<32 | ~idx), 1 STS.64 per warp,
//    2x LDS.128 + 3 u64 max-compares (ties auto-resolve to min idx).
// ---------------------------------------------------------------------------
__global__ __launch_bounds__(128, 1)
void fps_kernel(const float* __restrict__ vert, float* __restrict__ vpool) {
    __shared__ __align__(16) ull s_key[2][4];

    const int b    = blockIdx.x;
    const int tid  = threadIdx.x;
    const int lane = tid & 31;

    const float* vb = vert + (long)b * 3 * N_;

    // coalesced float4 loads: thread owns points 32*tid .. 32*tid+31
    // packed reg k: lo = local point 2k, hi = local point 2k+1
    ull xp[16], yp[16], zp[16];
#pragma unroll
    for (int q = 0; q < 8; ++q) {
        const float4 xv = *(const float4*)(vb + 32 * tid + 4 * q);
        const float4 yv = *(const float4*)(vb + N_ + 32 * tid + 4 * q);
        const float4 zv = *(const float4*)(vb + 2 * N_ + 32 * tid + 4 * q);
        xp[2 * q] = pack2(xv.x, xv.y); xp[2 * q + 1] = pack2(xv.z, xv.w);
        yp[2 * q] = pack2(yv.x, yv.y); yp[2 * q + 1] = pack2(yv.z, yv.w);
        zp[2 * q] = pack2(zv.x, zv.y); zp[2 * q + 1] = pack2(zv.z, zv.w);
    }

    float d[32];
#pragma unroll
    for (int j = 0; j < 32; ++j) d[j] = 1e10f;

    // Seed: centroid 0 is point 0 — all threads read it straight from gmem
    // (L1/L2 broadcast, one time). Matches the reference scan start.
    float cx = __ldg(vb);
    float cy = __ldg(vb + N_);
    float cz = __ldg(vb + 2 * N_);
    if (tid == 0) {
        g_cents[b * NPOINT_] = 0;
        vpool[((long)b * 3 + 0) * NPOINT_] = cx;
        vpool[((long)b * 3 + 1) * NPOINT_] = cy;
        vpool[((long)b * 3 + 2) * NPOINT_] = cz;
    }

    for (int it = 1; it < NPOINT_; ++it) {
        const int P = it & 1;

        const ull c2x = pack2(cx, cx);
        const ull c2y = pack2(cy, cy);
        const ull c2z = pack2(cz, cz);

        // dist = (dx*dx + dy*dy) + dz*dz, two points per packed op, exact rn;
        // running min scalar (FMNMX selects exactly; constant indices only)
#pragma unroll
        for (int k = 0; k < 16; ++k) {
            ull t, s;
            float q0, q1;
            t = sub2(xp[k], c2x); s = mul2(t, t);
            t = sub2(yp[k], c2y); s = add2(s, mul2(t, t));
            t = sub2(zp[k], c2z); s = add2(s, mul2(t, t));
            unpack2(s, q0, q1);
            d[2 * k]     = fminf(d[2 * k], q0);
            d[2 * k + 1] = fminf(d[2 * k + 1], q1);
        }

        // scalar max tree (max is exact & associative -> any shape OK)
        float m0 = fmaxf(fmaxf(fmaxf(d[0], d[1]),  fmaxf(d[2], d[3])),
                         fmaxf(fmaxf(d[4], d[5]),  fmaxf(d[6], d[7])));
        float m1 = fmaxf(fmaxf(fmaxf(d[8], d[9]),  fmaxf(d[10], d[11])),
                         fmaxf(fmaxf(d[12], d[13]), fmaxf(d[14], d[15])));
        float m2 = fmaxf(fmaxf(fmaxf(d[16], d[17]), fmaxf(d[18], d[19])),
                         fmaxf(fmaxf(d[20], d[21]), fmaxf(d[22], d[23])));
        float m3 = fmaxf(fmaxf(fmaxf(d[24], d[25]), fmaxf(d[26], d[27])),
                         fmaxf(fmaxf(d[28], d[29]), fmaxf(d[30], d[31])));
        const float bestv = fmaxf(fmaxf(m0, m1), fmaxf(m2, m3));
        const unsigned bv = __float_as_uint(bestv);   // >= +0 -> monotonic bits

        // REDUX #1 (max value over warp); the local-index mask below is
        // independent alu work that overlaps its latency.
        const unsigned wmax = __reduce_max_sync(0xffffffffu, bv);

        // first-occurrence local index: flat 32-bit equality mask + ffs
        // (constant indices only -> register-resident)
        unsigned em = 0u;
#pragma unroll
        for (int j = 0; j < 32; ++j)
            em |= (__float_as_uint(d[j]) == bv) ? (1u << j) : 0u;
        const int myn = (tid << 5) | (__ffs(em) - 1);   // em != 0 by construction

        // REDUX #2: max(~idx) among value-ties == min idx (first occurrence)
        const unsigned cand = (bv == wmax) ? ~(unsigned)myn : 0u;
        const unsigned winv = __reduce_max_sync(0xffffffffu, cand);

        if (lane == 0)
            s_key[P][tid >> 5] = ((ull)wmax << 32) | winv;   // @p STS.64
        __syncthreads();   // the ONLY barrier per iteration (ping-pong buffers)

        // block level: 3 packed max-compares; tie -> larger ~idx -> smaller idx
        const ulonglong2 kA = *(const ulonglong2*)&s_key[P][0];  // LDS.128
        const ulonglong2 kB = *(const ulonglong2*)&s_key[P][2];  // LDS.128
        const ull k01 = (kA.x >= kA.y) ? kA.x : kA.y;
        const ull k23 = (kB.x >= kB.y) ? kB.x : kB.y;
        const ull kw  = (k01 >= k23) ? k01 : k23;
        const int nwin = (int)(~(unsigned)kw);

        // centroid coords: uniform L1-hit broadcast loads (rows are warm)
        cx = __ldg(vb + nwin);
        cy = __ldg(vb + N_ + nwin);
        cz = __ldg(vb + 2 * N_ + nwin);

        if (tid == 0) {
            g_cents[b * NPOINT_ + it] = nwin;
            vpool[((long)b * 3 + 0) * NPOINT_ + it] = cx;
            vpool[((long)b * 3 + 1) * NPOINT_ + it] = cy;
            vpool[((long)b * 3 + 2) * NPOINT_ + it] = cz;
        }
    }
}

// ---------------------------------------------------------------------------
// Kernel C: gather K neighbors of each sampled point from fmT, max-pool over K,
// write feature_map_pool (B,C,NPOINT). One block per sampled point, c = tid.
// idx dtype (int32 vs int64) detected from data: int64 high words are all 0.
// idx values for a point are contiguous -> vector-load them once into a
// constant-indexed register array, then gather.
// ---------------------------------------------------------------------------
__global__ void gather_max_kernel(const void* __restrict__ idxp,
                                  float* __restrict__ fpool) {
    const int bp = blockIdx.x;            // 0 .. B*NPOINT-1
    const int b  = bp >> 10;              // / NPOINT_
    const int i  = bp & (NPOINT_ - 1);
    const int c  = threadIdx.x;

    const int s = g_cents[bp];

    const int* i32 = (const int*)idxp;
    const bool is64 = ((i32[1] | i32[3] | i32[5]) == 0);

    const long base = ((long)(b * N_ + s)) * K_;   // element index, multiple of 16

    long g[K_];
    if (is64) {
        const longlong2* p = (const longlong2*)idxp + (base >> 1);
#pragma unroll
        for (int q = 0; q < 8; ++q) {
            const longlong2 v = __ldg(p + q);
            g[2 * q] = (long)v.x; g[2 * q + 1] = (long)v.y;
        }
    } else {
        const int4* p = (const int4*)idxp + (base >> 2);
#pragma unroll
        for (int q = 0; q < 4; ++q) {
            const int4 v = __ldg(p + q);
            g[4 * q] = v.x; g[4 * q + 1] = v.y;
            g[4 * q + 2] = v.z; g[4 * q + 3] = v.w;
        }
    }

    float m = -3.4028235e38f;
#pragma unroll
    for (int k = 0; k < K_; ++k)
        m = fmaxf(m, g_fmT[g[k] * C_ + c]);
    fpool[((long)b * C_ + c) * NPOINT_ + i] = m;
}

// ---------------------------------------------------------------------------
extern "C" void kernel_launch(void* const* d_in, const int* in_sizes, int n_in,
                              void* d_out, int out_size) {
    const float* vert = (const float*)d_in[0];   // (B,3,N)   float32
    const float* fm   = (const float*)d_in[1];   // (B,C,N)   float32
    const void*  idx  = d_in[2];                 // (B*N*K,)  int64 or int32

    float* out   = (float*)d_out;
    float* vpool = out;                          // (B,3,NPOINT)
    float* fpool = out + (long)B_ * 3 * NPOINT_; // (B,C,NPOINT)

    transpose_kernel<<<dim3(N_ / 32, C_ / 32, B_), dim3(32, 8)>>>(fm);
    fps_kernel<<<B_, 128>>>(vert, vpool);
    gather_max_kernel<<<B_ * NPOINT_, C_>>>(idx, fpool);
}